// round 7
// baseline (speedup 1.0000x reference)
#include <cuda_runtime.h>
#include <math.h>
#include <stddef.h>
#include <stdint.h>

#define BB   2
#define SS   1024
#define DD   1024
#define HH   16
#define DKK  64
#define LL   4
#define DFFN 4096
#define OUTV 32000
#define MTOK (BB*SS)

// ---------------- scratch (allocation-free: __device__ globals) ----------------
__device__ float g_h [MTOK*DD];
__device__ float g_ht[MTOK*DD];
__device__ float g_q [MTOK*DD];
__device__ float g_k [MTOK*DD];
__device__ float g_v [MTOK*DD];
__device__ float g_attn[MTOK*DD];
__device__ float g_ffn[(size_t)MTOK*DFFN];
__device__ float g_part[(size_t)4*MTOK*DD];      // split-K partials (32 MB)

// ---------------- helpers ----------------
__device__ __forceinline__ float tf32r(float x) {
    uint32_t u;
    asm("cvt.rna.tf32.f32 %0, %1;" : "=r"(u) : "f"(x));
    return __uint_as_float(u);
}
__device__ __forceinline__ void mma_tf32(float* c, const uint32_t* a, const uint32_t* b) {
    asm volatile(
        "mma.sync.aligned.m16n8k8.row.col.f32.tf32.tf32.f32 "
        "{%0,%1,%2,%3}, {%4,%5,%6,%7}, {%8,%9}, {%0,%1,%2,%3};"
        : "+f"(c[0]), "+f"(c[1]), "+f"(c[2]), "+f"(c[3])
        : "r"(a[0]), "r"(a[1]), "r"(a[2]), "r"(a[3]), "r"(b[0]), "r"(b[1]));
}
__device__ __forceinline__ void ldsm4(uint32_t* r, uint32_t addr) {
    asm volatile("ldmatrix.sync.aligned.m8n8.x4.shared.b16 {%0,%1,%2,%3}, [%4];"
        : "=r"(r[0]), "=r"(r[1]), "=r"(r[2]), "=r"(r[3]) : "r"(addr));
}
__device__ __forceinline__ void cp16(uint32_t s, const void* g) {
    asm volatile("cp.async.cg.shared.global [%0], [%1], 16;" :: "r"(s), "l"(g));
}
#define CP_COMMIT() asm volatile("cp.async.commit_group;")
#define CP_WAIT1()  asm volatile("cp.async.wait_group 1;")

// ---------------- embedding (writes fp32 h and tf32-rounded ht) -----------------
__global__ void embed_kernel(const int* __restrict__ x, const float* __restrict__ emb,
                             float* __restrict__ h, float* __restrict__ ht) {
    int r = blockIdx.x;
    int tok = x[r];
    const float4* src = (const float4*)(emb + (size_t)tok * DD);
    float4 v = src[threadIdx.x];
    v.x *= 32.0f; v.y *= 32.0f; v.z *= 32.0f; v.w *= 32.0f;   // sqrt(1024)
    ((float4*)(h + (size_t)r * DD))[threadIdx.x] = v;
    float4 t = make_float4(tf32r(v.x), tf32r(v.y), tf32r(v.z), tf32r(v.w));
    ((float4*)(ht + (size_t)r * DD))[threadIdx.x] = t;
}

// =================================================================================
// Dense tf32 GEMM: 128x128x32 tiles, 3-stage cp.async (107.5KB smem, 2 CTA/SM),
// 8 warps 2x4, warp 64x32, A frags via ldmatrix.x4, one __syncthreads per chunk.
// mode bit0: gelu, bit1: start_pos mask, bit2: round output to tf32.
// czstride==0: blockIdx.z selects B/bias/C pointer set (QKV fusion), K = Ksplit.
// czstride!=0: split-K: z = split index; C = C0 + z*czstride; bias applied later.
// =================================================================================
#define ASZ (128*36)
#define BSZ (32*136)
#define GEMM_SMEM (3*(ASZ+BSZ)*4)

__global__ void __launch_bounds__(256,2) gemm_tc(
    const float* __restrict__ A,
    const float* __restrict__ B0, const float* __restrict__ bias0, float* __restrict__ C0,
    const float* __restrict__ B1, const float* __restrict__ bias1, float* __restrict__ C1,
    const float* __restrict__ B2, const float* __restrict__ bias2, float* __restrict__ C2,
    int Ksplit, int lda, int ldb, int ldc, int mode,
    const int* __restrict__ sp, size_t czstride)
{
    const float* Bm = B0; const float* bias = bias0; float* C = C0;
    int kbase = 0;
    if (czstride) {
        C = C0 + (size_t)blockIdx.z * czstride;
        kbase = blockIdx.z * Ksplit;
        bias = 0;
    } else {
        if (blockIdx.z == 1) { Bm = B1; bias = bias1; C = C1; }
        else if (blockIdx.z == 2) { Bm = B2; bias = bias2; C = C2; }
    }

    extern __shared__ float sm[];
    float* Bs = sm + 3*ASZ;

    int tid = threadIdx.x;
    int lane = tid & 31, warp = tid >> 5;
    int wm = warp >> 2, wn = warp & 3;
    int g = lane >> 2, tg = lane & 3;
    int row0 = blockIdx.x*128, col0 = blockIdx.y*128;

    const float* Abase = A + (size_t)row0 * lda + kbase;
    const float* Bbase = Bm + (size_t)kbase * ldb + col0;

    int a_r = tid >> 3, a_c = (tid & 7) << 2;
    int b_r = tid >> 5, b_c = (tid & 31) << 2;
    uint32_t sA = (uint32_t)__cvta_generic_to_shared(sm);
    uint32_t sB = (uint32_t)__cvta_generic_to_shared(Bs);

    int lrow = lane & 15, lcol = (lane >> 4) << 2;

    int nch = Ksplit >> 5;

    #pragma unroll
    for (int s = 0; s < 2; s++) {
        int k0 = s << 5;
        uint32_t dA = sA + (uint32_t)(s*ASZ) * 4;
        uint32_t dB = sB + (uint32_t)(s*BSZ) * 4;
        #pragma unroll
        for (int p = 0; p < 4; p++) {
            int r = a_r + 32*p;
            cp16(dA + (uint32_t)(r*36 + a_c)*4, Abase + (size_t)r*lda + k0 + a_c);
        }
        #pragma unroll
        for (int p = 0; p < 4; p++) {
            int r = b_r + 8*p;
            cp16(dB + (uint32_t)(r*136 + b_c)*4, Bbase + (size_t)(k0 + r)*ldb + b_c);
        }
        CP_COMMIT();
    }

    float acc[4][4][4] = {};

    for (int ch = 0; ch < nch; ch++) {
        CP_WAIT1();
        __syncthreads();
        if (ch + 2 < nch) {
            int s = (ch + 2) % 3, k0 = (ch + 2) << 5;
            uint32_t dA = sA + (uint32_t)(s*ASZ) * 4;
            uint32_t dB = sB + (uint32_t)(s*BSZ) * 4;
            #pragma unroll
            for (int p = 0; p < 4; p++) {
                int r = a_r + 32*p;
                cp16(dA + (uint32_t)(r*36 + a_c)*4, Abase + (size_t)r*lda + k0 + a_c);
            }
            #pragma unroll
            for (int p = 0; p < 4; p++) {
                int r = b_r + 8*p;
                cp16(dB + (uint32_t)(r*136 + b_c)*4, Bbase + (size_t)(k0 + r)*ldb + b_c);
            }
        }
        CP_COMMIT();

        uint32_t asw = sA + (uint32_t)((ch % 3)*ASZ)*4;
        const float* bs = Bs + (ch % 3)*BSZ;
        #pragma unroll
        for (int ks = 0; ks < 4; ks++) {
            int kc = ks << 3;
            uint32_t af[4][4], bf[4][2];
            #pragma unroll
            for (int m = 0; m < 4; m++) {
                uint32_t addr = asw + (uint32_t)((wm*64 + m*16 + lrow)*36 + kc + lcol)*4;
                ldsm4(af[m], addr);
            }
            #pragma unroll
            for (int n = 0; n < 4; n++) {
                const float* p = bs + (kc + tg)*136 + wn*32 + n*8 + g;
                bf[n][0] = __float_as_uint(tf32r(p[0]));
                bf[n][1] = __float_as_uint(tf32r(p[4*136]));
            }
            #pragma unroll
            for (int m = 0; m < 4; m++)
                #pragma unroll
                for (int n = 0; n < 4; n++)
                    mma_tf32(acc[m][n], af[m], bf[n]);
        }
    }

    #pragma unroll
    for (int m = 0; m < 4; m++) {
        int r0 = row0 + wm*64 + m*16 + g;
        #pragma unroll
        for (int n = 0; n < 4; n++) {
            int c = col0 + wn*32 + n*8 + tg*2;
            float b0f = bias ? bias[c] : 0.0f;
            float b1f = bias ? bias[c + 1] : 0.0f;
            float v[4] = { acc[m][n][0] + b0f, acc[m][n][1] + b1f,
                           acc[m][n][2] + b0f, acc[m][n][3] + b1f };
            if (mode & 1) {
                #pragma unroll
                for (int i = 0; i < 4; i++)
                    v[i] = 0.5f * v[i] * (1.0f + erff(v[i] * 0.70710678118654752f));
            }
            if (mode & 2) {
                int r1 = r0 + 8;
                if ((r0 & 1023) < sp[r0 >> 10]) { v[0] = 0.0f; v[1] = 0.0f; }
                if ((r1 & 1023) < sp[r1 >> 10]) { v[2] = 0.0f; v[3] = 0.0f; }
            }
            if (mode & 4) {
                #pragma unroll
                for (int i = 0; i < 4; i++) v[i] = tf32r(v[i]);
            }
            *(float2*)&C[(size_t)r0 * ldc + c]       = make_float2(v[0], v[1]);
            *(float2*)&C[(size_t)(r0 + 8) * ldc + c] = make_float2(v[2], v[3]);
        }
    }
}

// =================================================================================
// Flash attention (unchanged)
// =================================================================================
#define FA_LDK 72
#define FA_LDP 132
#define FA_KV (128*FA_LDK)
#define FA_SMEM ((4*FA_KV + 128*FA_LDP)*4)

__global__ void __launch_bounds__(256,1) flash_attn(
    const float* __restrict__ Q, const float* __restrict__ Kg,
    const float* __restrict__ Vg, float* __restrict__ O,
    const int* __restrict__ sp)
{
    int z = blockIdx.z, bi = z >> 4, hi = z & 15;
    int q0 = blockIdx.x * 128;
    const float* Qb = Q  + (size_t)bi*SS*DD + hi*DKK;
    const float* Kb = Kg + (size_t)bi*SS*DD + hi*DKK;
    const float* Vb = Vg + (size_t)bi*SS*DD + hi*DKK;
    float* Ob = O + (size_t)bi*SS*DD + hi*DKK;

    extern __shared__ float sm[];
    float* Ks = sm;
    float* Vs = sm + 2*FA_KV;
    float* Ps = sm + 4*FA_KV;
    uint32_t sBase = (uint32_t)__cvta_generic_to_shared(sm);

    int tid = threadIdx.x;
    int lane = tid & 31, warp = tid >> 5;
    int g = lane >> 2, tg = lane & 3;
    int wq = warp * 16;
    int spv = sp[bi];
    float slope = exp2f(-0.5f * (float)(hi + 1));

    #pragma unroll
    for (int p = 0; p < 8; p++) {
        int i = tid + (p << 8);
        int r = i >> 4, c = (i & 15) << 2;
        *(float4*)&Ps[r*FA_LDK + c] = *(const float4*)(Qb + (size_t)(q0 + r)*DD + c);
    }
    __syncthreads();
    uint32_t aq[8][4];
    #pragma unroll
    for (int kf = 0; kf < 8; kf++) {
        const float* p = Ps + (wq + g)*FA_LDK + kf*8 + tg;
        aq[kf][0] = __float_as_uint(p[0]);
        aq[kf][1] = __float_as_uint(p[8*FA_LDK]);
        aq[kf][2] = __float_as_uint(p[4]);
        aq[kf][3] = __float_as_uint(p[8*FA_LDK + 4]);
    }
    __syncthreads();

    int nt = (q0 >= 256) ? (q0 >> 7) + 1 : 8;

    {
        #pragma unroll
        for (int p = 0; p < 8; p++) {
            int i = tid + (p << 8);
            int r = i >> 4, c = (i & 15) << 2;
            cp16(sBase + (uint32_t)(r*FA_LDK + c)*4,            Kb + (size_t)r*DD + c);
            cp16(sBase + (uint32_t)(2*FA_KV + r*FA_LDK + c)*4,  Vb + (size_t)r*DD + c);
        }
        CP_COMMIT();
    }

    float m_i[2] = {-1e30f, -1e30f};
    float l_i[2] = {0.0f, 0.0f};
    float acc_o[8][4] = {};
    float* Pw = Ps + wq*FA_LDP;

    for (int t = 0; t < nt; t++) {
        __syncthreads();
        if (t + 1 < nt) {
            int st = (t + 1) & 1;
            const float* Kt = Kb + (size_t)((t+1) << 7)*DD;
            const float* Vt = Vb + (size_t)((t+1) << 7)*DD;
            #pragma unroll
            for (int p = 0; p < 8; p++) {
                int i = tid + (p << 8);
                int r = i >> 4, c = (i & 15) << 2;
                cp16(sBase + (uint32_t)(st*FA_KV + r*FA_LDK + c)*4,     Kt + (size_t)r*DD + c);
                cp16(sBase + (uint32_t)((2+st)*FA_KV + r*FA_LDK + c)*4, Vt + (size_t)r*DD + c);
            }
        }
        CP_COMMIT();
        CP_WAIT1();
        __syncthreads();

        const float* ks = Ks + (t & 1)*FA_KV;
        const float* vs = Vs + (t & 1)*FA_KV;

        float acc_s[16][4] = {};
        #pragma unroll
        for (int kf = 0; kf < 8; kf++) {
            int kc = kf << 3;
            #pragma unroll
            for (int nf = 0; nf < 16; nf++) {
                uint32_t bf[2];
                const float* p = ks + (nf*8 + g)*FA_LDK + kc + tg;
                bf[0] = __float_as_uint(p[0]);
                bf[1] = __float_as_uint(p[4]);
                mma_tf32(acc_s[nf], aq[kf], bf);
            }
        }

        int c0 = t << 7;
        int qr0 = q0 + wq + g, qr1 = qr0 + 8;
        float tm0 = -1e30f, tm1 = -1e30f;
        #pragma unroll
        for (int nf = 0; nf < 16; nf++) {
            int c = c0 + nf*8 + tg*2;
            #pragma unroll
            for (int j = 0; j < 2; j++) {
                int cc = c + j;
                float s0 = acc_s[nf][j]   * 0.125f + slope * (float)(cc - qr0);
                float s1 = acc_s[nf][j+2] * 0.125f + slope * (float)(cc - qr1);
                bool ok0 = (qr0 >= cc) || (qr0 < spv) || (cc < spv);
                bool ok1 = (qr1 >= cc) || (qr1 < spv) || (cc < spv);
                acc_s[nf][j]   = ok0 ? s0 : -1e9f;
                acc_s[nf][j+2] = ok1 ? s1 : -1e9f;
                tm0 = fmaxf(tm0, acc_s[nf][j]);
                tm1 = fmaxf(tm1, acc_s[nf][j+2]);
            }
        }
        tm0 = fmaxf(tm0, __shfl_xor_sync(0xffffffffu, tm0, 1));
        tm0 = fmaxf(tm0, __shfl_xor_sync(0xffffffffu, tm0, 2));
        tm1 = fmaxf(tm1, __shfl_xor_sync(0xffffffffu, tm1, 1));
        tm1 = fmaxf(tm1, __shfl_xor_sync(0xffffffffu, tm1, 2));

        float mn0 = fmaxf(m_i[0], tm0), mn1 = fmaxf(m_i[1], tm1);
        float al0 = expf(m_i[0] - mn0),  al1 = expf(m_i[1] - mn1);
        m_i[0] = mn0; m_i[1] = mn1;

        float rs0 = 0.0f, rs1 = 0.0f;
        #pragma unroll
        for (int nf = 0; nf < 16; nf++) {
            float p0 = expf(acc_s[nf][0] - mn0);
            float p1 = expf(acc_s[nf][1] - mn0);
            float p2 = expf(acc_s[nf][2] - mn1);
            float p3 = expf(acc_s[nf][3] - mn1);
            rs0 += p0 + p1; rs1 += p2 + p3;
            int col = nf*8 + tg*2;
            *(float2*)&Pw[g*FA_LDP + col]       = make_float2(tf32r(p0), tf32r(p1));
            *(float2*)&Pw[(g+8)*FA_LDP + col]   = make_float2(tf32r(p2), tf32r(p3));
        }
        rs0 += __shfl_xor_sync(0xffffffffu, rs0, 1);
        rs0 += __shfl_xor_sync(0xffffffffu, rs0, 2);
        rs1 += __shfl_xor_sync(0xffffffffu, rs1, 1);
        rs1 += __shfl_xor_sync(0xffffffffu, rs1, 2);
        l_i[0] = l_i[0]*al0 + rs0;
        l_i[1] = l_i[1]*al1 + rs1;

        #pragma unroll
        for (int nf = 0; nf < 8; nf++) {
            acc_o[nf][0] *= al0; acc_o[nf][1] *= al0;
            acc_o[nf][2] *= al1; acc_o[nf][3] *= al1;
        }
        __syncwarp();

        #pragma unroll
        for (int kf = 0; kf < 16; kf++) {
            int kc = kf << 3;
            uint32_t af[4];
            const float* p = Pw + g*FA_LDP + kc + tg;
            af[0] = __float_as_uint(p[0]);
            af[1] = __float_as_uint(p[8*FA_LDP]);
            af[2] = __float_as_uint(p[4]);
            af[3] = __float_as_uint(p[8*FA_LDP + 4]);
            #pragma unroll
            for (int nf = 0; nf < 8; nf++) {
                uint32_t bf[2];
                const float* q2 = vs + (kc + tg)*FA_LDK + nf*8 + g;
                bf[0] = __float_as_uint(q2[0]);
                bf[1] = __float_as_uint(q2[4*FA_LDK]);
                mma_tf32(acc_o[nf], af, bf);
            }
        }
        __syncwarp();
    }

    float inv0 = 1.0f / l_i[0], inv1 = 1.0f / l_i[1];
    int qr0 = q0 + wq + g;
    #pragma unroll
    for (int nf = 0; nf < 8; nf++) {
        int c = nf*8 + tg*2;
        *(float2*)&Ob[(size_t)qr0*DD + c] =
            make_float2(tf32r(acc_o[nf][0]*inv0), tf32r(acc_o[nf][1]*inv0));
        *(float2*)&Ob[(size_t)(qr0+8)*DD + c] =
            make_float2(tf32r(acc_o[nf][2]*inv1), tf32r(acc_o[nf][3]*inv1));
    }
}

// --------- residual + (sum of split-K partials) + bias, then layernorm -----------
__global__ void __launch_bounds__(256) add_ln_red(
    const float* __restrict__ X, const float* __restrict__ parts, int nparts,
    const float* __restrict__ bias,
    const float* __restrict__ g, const float* __restrict__ bta,
    float* __restrict__ out, float* __restrict__ out_t)
{
    int r = blockIdx.x, tid = threadIdx.x;
    float4 xv = ((const float4*)(X + (size_t)r * DD))[tid];
    float v0 = xv.x, v1 = xv.y, v2 = xv.z, v3 = xv.w;
    for (int i = 0; i < nparts; i++) {
        float4 pv = ((const float4*)(parts + (size_t)i*MTOK*DD + (size_t)r*DD))[tid];
        v0 += pv.x; v1 += pv.y; v2 += pv.z; v3 += pv.w;
    }
    float4 bb = ((const float4*)bias)[tid];
    v0 += bb.x; v1 += bb.y; v2 += bb.z; v3 += bb.w;

    float s1 = v0 + v1 + v2 + v3;
    float s2 = v0*v0 + v1*v1 + v2*v2 + v3*v3;

    __shared__ float rA[256], rB[256];
    rA[tid] = s1; rB[tid] = s2; __syncthreads();
    for (int s = 128; s > 0; s >>= 1) {
        if (tid < s) { rA[tid] += rA[tid + s]; rB[tid] += rB[tid + s]; }
        __syncthreads();
    }
    float mu = rA[0] * (1.0f / 1024.0f);
    float var = rB[0] * (1.0f / 1024.0f) - mu * mu;
    float rstd = rsqrtf(var + 1e-5f);

    const float4 gv = ((const float4*)g)[tid];
    const float4 bv = ((const float4*)bta)[tid];
    float4 o;
    o.x = (v0 - mu) * rstd * gv.x + bv.x;
    o.y = (v1 - mu) * rstd * gv.y + bv.y;
    o.z = (v2 - mu) * rstd * gv.z + bv.z;
    o.w = (v3 - mu) * rstd * gv.w + bv.w;
    ((float4*)(out + (size_t)r * DD))[tid] = o;
    float4 t = make_float4(tf32r(o.x), tf32r(o.y), tf32r(o.z), tf32r(o.w));
    ((float4*)(out_t + (size_t)r * DD))[tid] = t;
}

// ---------------- launch ----------------
extern "C" void kernel_launch(void* const* d_in, const int* in_sizes, int n_in,
                              void* d_out, int out_size) {
    (void)in_sizes; (void)n_in; (void)out_size;
    const int*   x    = (const int*)  d_in[0];
    const int*   sp   = (const int*)  d_in[1];
    const float* emb  = (const float*)d_in[2];
    const float* Wq   = (const float*)d_in[3];
    const float* bq   = (const float*)d_in[4];
    const float* Wk   = (const float*)d_in[5];
    const float* bk   = (const float*)d_in[6];
    const float* Wv   = (const float*)d_in[7];
    const float* bv   = (const float*)d_in[8];
    const float* Wo   = (const float*)d_in[9];
    const float* bo   = (const float*)d_in[10];
    const float* ln1g = (const float*)d_in[11];
    const float* ln1b = (const float*)d_in[12];
    const float* W1   = (const float*)d_in[13];
    const float* b1   = (const float*)d_in[14];
    const float* W2   = (const float*)d_in[15];
    const float* b2   = (const float*)d_in[16];
    const float* ln2g = (const float*)d_in[17];
    const float* ln2b = (const float*)d_in[18];
    const float* fcw  = (const float*)d_in[19];
    const float* fcb  = (const float*)d_in[20];
    float* out = (float*)d_out;

    float *h, *ht, *q, *k, *v, *attn, *ffn, *part;
    cudaGetSymbolAddress((void**)&h,    g_h);
    cudaGetSymbolAddress((void**)&ht,   g_ht);
    cudaGetSymbolAddress((void**)&q,    g_q);
    cudaGetSymbolAddress((void**)&k,    g_k);
    cudaGetSymbolAddress((void**)&v,    g_v);
    cudaGetSymbolAddress((void**)&attn, g_attn);
    cudaGetSymbolAddress((void**)&ffn,  g_ffn);
    cudaGetSymbolAddress((void**)&part, g_part);

    static int attr_done = 0;
    if (!attr_done) {
        cudaFuncSetAttribute(gemm_tc,    cudaFuncAttributeMaxDynamicSharedMemorySize, GEMM_SMEM);
        cudaFuncSetAttribute(flash_attn, cudaFuncAttributeMaxDynamicSharedMemorySize, FA_SMEM);
        attr_done = 1;
    }

    const float* NUL = 0;
    float* NULF = 0;
    size_t PZ = (size_t)MTOK*DD;

    embed_kernel<<<MTOK, 256>>>(x, emb, h, ht);

    for (int l = 0; l < LL; l++) {
        const float* Wql = Wq + (size_t)l * DD * DD;
        const float* Wkl = Wk + (size_t)l * DD * DD;
        const float* Wvl = Wv + (size_t)l * DD * DD;
        const float* Wol = Wo + (size_t)l * DD * DD;
        const float* W1l = W1 + (size_t)l * DD * DFFN;
        const float* W2l = W2 + (size_t)l * DFFN * DD;

        // fused QKV (grid 384)
        gemm_tc<<<dim3(MTOK/128, DD/128, 3), 256, GEMM_SMEM>>>(
            ht,
            Wql, bq + (size_t)l*DD, q,
            Wkl, bk + (size_t)l*DD, k,
            Wvl, bv + (size_t)l*DD, v,
            DD, DD, DD, DD, 4, (const int*)0, 0);

        flash_attn<<<dim3(SS/128, 1, BB*HH), 256, FA_SMEM>>>(q, k, v, attn, sp);

        // Wo: split-K x4 (grid 512)
        gemm_tc<<<dim3(MTOK/128, DD/128, 4), 256, GEMM_SMEM>>>(
            attn, Wol, NUL, part, NUL, NUL, NULF, NUL, NUL, NULF,
            DD/4, DD, DD, DD, 0, (const int*)0, PZ);
        add_ln_red<<<MTOK, 256>>>(h, part, 4, bo + (size_t)l*DD,
            ln1g + (size_t)l*DD, ln1b + (size_t)l*DD, h, ht);

        // W1 + gelu (grid 512)
        gemm_tc<<<dim3(MTOK/128, DFFN/128, 1), 256, GEMM_SMEM>>>(
            ht, W1l, b1 + (size_t)l*DFFN, ffn, NUL, NUL, NULF, NUL, NUL, NULF,
            DD, DD, DFFN, DFFN, 1 | 4, (const int*)0, 0);

        // W2: split-K x4 (grid 512)
        gemm_tc<<<dim3(MTOK/128, DD/128, 4), 256, GEMM_SMEM>>>(
            ffn, W2l, NUL, part, NUL, NUL, NULF, NUL, NUL, NULF,
            DFFN/4, DFFN, DD, DD, 0, (const int*)0, PZ);
        add_ln_red<<<MTOK, 256>>>(h, part, 4, b2 + (size_t)l*DD,
            ln2g + (size_t)l*DD, ln2b + (size_t)l*DD, h, ht);
    }

    // LM head (grid 4000)
    gemm_tc<<<dim3(MTOK/128, OUTV/128, 1), 256, GEMM_SMEM>>>(
        ht, fcw, fcb, out, NUL, NUL, NULF, NUL, NUL, NULF,
        DD, DD, OUTV, OUTV, 2, sp, 0);
}

// round 8
// speedup vs baseline: 1.0495x; 1.0495x over previous
#include <cuda_runtime.h>
#include <math.h>
#include <stddef.h>
#include <stdint.h>

#define BB   2
#define SS   1024
#define DD   1024
#define HH   16
#define DKK  64
#define LL   4
#define DFFN 4096
#define OUTV 32000
#define MTOK (BB*SS)

// ---------------- scratch (allocation-free: __device__ globals) ----------------
__device__ float g_h [MTOK*DD];
__device__ float g_ht[MTOK*DD];
__device__ float g_q [MTOK*DD];
__device__ float g_k [MTOK*DD];
__device__ float g_v [MTOK*DD];
__device__ float g_attn[MTOK*DD];
__device__ float g_tmp [MTOK*DD];
__device__ float g_ffn[(size_t)MTOK*DFFN];

// ---------------- helpers ----------------
__device__ __forceinline__ float tf32r(float x) {
    uint32_t u;
    asm("cvt.rna.tf32.f32 %0, %1;" : "=r"(u) : "f"(x));
    return __uint_as_float(u);
}
__device__ __forceinline__ void mma_tf32(float* c, const uint32_t* a, const uint32_t* b) {
    asm volatile(
        "mma.sync.aligned.m16n8k8.row.col.f32.tf32.tf32.f32 "
        "{%0,%1,%2,%3}, {%4,%5,%6,%7}, {%8,%9}, {%0,%1,%2,%3};"
        : "+f"(c[0]), "+f"(c[1]), "+f"(c[2]), "+f"(c[3])
        : "r"(a[0]), "r"(a[1]), "r"(a[2]), "r"(a[3]), "r"(b[0]), "r"(b[1]));
}
__device__ __forceinline__ void ldsm4(uint32_t* r, uint32_t addr) {
    asm volatile("ldmatrix.sync.aligned.m8n8.x4.shared.b16 {%0,%1,%2,%3}, [%4];"
        : "=r"(r[0]), "=r"(r[1]), "=r"(r[2]), "=r"(r[3]) : "r"(addr));
}
__device__ __forceinline__ void cp16(uint32_t s, const void* g) {
    asm volatile("cp.async.cg.shared.global [%0], [%1], 16;" :: "r"(s), "l"(g));
}
#define CP_COMMIT() asm volatile("cp.async.commit_group;")
#define CP_WAIT2()  asm volatile("cp.async.wait_group 2;")
#define CP_WAIT1()  asm volatile("cp.async.wait_group 1;")

// ---------------- embedding (writes fp32 h and tf32-rounded ht) -----------------
__global__ void embed_kernel(const int* __restrict__ x, const float* __restrict__ emb,
                             float* __restrict__ h, float* __restrict__ ht) {
    int r = blockIdx.x;
    int tok = x[r];
    const float4* src = (const float4*)(emb + (size_t)tok * DD);
    float4 v = src[threadIdx.x];
    v.x *= 32.0f; v.y *= 32.0f; v.z *= 32.0f; v.w *= 32.0f;   // sqrt(1024)
    ((float4*)(h + (size_t)r * DD))[threadIdx.x] = v;
    float4 t = make_float4(tf32r(v.x), tf32r(v.y), tf32r(v.z), tf32r(v.w));
    ((float4*)(ht + (size_t)r * DD))[threadIdx.x] = t;
}

// =================================================================================
// Dense tf32 GEMM: 128x128x32 tiles, 4-stage cp.async, 8 warps 2x4, warp 64x32.
// Register-double-buffered fragments: frags for step ks+1 (or next chunk's ks0)
// load while step ks's 16 MMAs issue -> load->MMA dependency bubble removed.
// One __syncthreads per chunk; wait_group 2 keeps chunks ch and ch+1 resident.
// mode bit0: gelu, bit1: start_pos mask, bit2: round output to tf32.
// blockIdx.z selects B/bias/C pointer set (QKV fusion).
// =================================================================================
#define NSTG 4
#define ASZ (128*36)
#define BSZ (32*136)
#define GEMM_SMEM (NSTG*(ASZ+BSZ)*4)

__global__ void __launch_bounds__(256) gemm_tc(
    const float* __restrict__ A,
    const float* __restrict__ B0, const float* __restrict__ bias0, float* __restrict__ C0,
    const float* __restrict__ B1, const float* __restrict__ bias1, float* __restrict__ C1,
    const float* __restrict__ B2, const float* __restrict__ bias2, float* __restrict__ C2,
    int K, int lda, int ldb, int ldc, int mode, const int* __restrict__ sp)
{
    const float* Bm = B0; const float* bias = bias0; float* C = C0;
    if (blockIdx.z == 1) { Bm = B1; bias = bias1; C = C1; }
    else if (blockIdx.z == 2) { Bm = B2; bias = bias2; C = C2; }

    extern __shared__ float sm[];
    float* Bs = sm + NSTG*ASZ;

    int tid = threadIdx.x;
    int lane = tid & 31, warp = tid >> 5;
    int wm = warp >> 2, wn = warp & 3;
    int g = lane >> 2, tg = lane & 3;
    int row0 = blockIdx.x*128, col0 = blockIdx.y*128;

    const float* Abase = A + (size_t)row0 * lda;
    const float* Bbase = Bm + col0;

    int a_r = tid >> 3, a_c = (tid & 7) << 2;
    int b_r = tid >> 5, b_c = (tid & 31) << 2;
    uint32_t sA = (uint32_t)__cvta_generic_to_shared(sm);
    uint32_t sB = (uint32_t)__cvta_generic_to_shared(Bs);

    int lrow = lane & 15, lcol = (lane >> 4) << 2;

    int nch = K >> 5;

#define ISSUE_STAGE(s_, k0_) do {                                              \
    uint32_t dA_ = sA + (uint32_t)((s_)*ASZ) * 4;                              \
    uint32_t dB_ = sB + (uint32_t)((s_)*BSZ) * 4;                              \
    _Pragma("unroll")                                                          \
    for (int p_ = 0; p_ < 4; p_++) {                                           \
        int r_ = a_r + 32*p_;                                                  \
        cp16(dA_ + (uint32_t)(r_*36 + a_c)*4, Abase + (size_t)r_*lda + (k0_) + a_c); \
    }                                                                          \
    _Pragma("unroll")                                                          \
    for (int p_ = 0; p_ < 4; p_++) {                                           \
        int r_ = b_r + 8*p_;                                                   \
        cp16(dB_ + (uint32_t)(r_*136 + b_c)*4, Bbase + (size_t)((k0_) + r_)*ldb + b_c); \
    }                                                                          \
} while (0)

    // prologue: stages 0,1,2
    #pragma unroll
    for (int s = 0; s < 3; s++) {
        ISSUE_STAGE(s, s << 5);
        CP_COMMIT();
    }
    CP_WAIT2();
    __syncthreads();

    float acc[4][4][4] = {};
    uint32_t afr[2][4][4], bfr[2][4][2];

#define LOADF(buf_, s_, kc_) do {                                              \
    uint32_t asw_ = sA + (uint32_t)((s_)*ASZ) * 4;                             \
    const float* bs_ = Bs + (s_)*BSZ;                                          \
    _Pragma("unroll")                                                          \
    for (int m_ = 0; m_ < 4; m_++) {                                           \
        uint32_t ad_ = asw_ + (uint32_t)((wm*64 + m_*16 + lrow)*36 + (kc_) + lcol)*4; \
        ldsm4(afr[buf_][m_], ad_);                                             \
    }                                                                          \
    _Pragma("unroll")                                                          \
    for (int n_ = 0; n_ < 4; n_++) {                                           \
        const float* p_ = bs_ + ((kc_) + tg)*136 + wn*32 + n_*8 + g;           \
        bfr[buf_][n_][0] = __float_as_uint(tf32r(p_[0]));                      \
        bfr[buf_][n_][1] = __float_as_uint(tf32r(p_[4*136]));                  \
    }                                                                          \
} while (0)

#define MMAALL(buf_) do {                                                      \
    _Pragma("unroll")                                                          \
    for (int m_ = 0; m_ < 4; m_++)                                             \
        _Pragma("unroll")                                                      \
        for (int n_ = 0; n_ < 4; n_++)                                         \
            mma_tf32(acc[m_][n_], afr[buf_][m_], bfr[buf_][n_]);               \
} while (0)

    LOADF(0, 0, 0);

    for (int ch = 0; ch < nch; ch++) {
        int st = ch & (NSTG - 1);
        LOADF(1, st, 8);   MMAALL(0);
        LOADF(0, st, 16);  MMAALL(1);
        LOADF(1, st, 24);  MMAALL(0);
        if (ch + 3 < nch) {
            ISSUE_STAGE((ch + 3) & (NSTG - 1), (ch + 3) << 5);
        }
        CP_COMMIT();
        CP_WAIT2();
        __syncthreads();
        if (ch + 1 < nch) LOADF(0, (ch + 1) & (NSTG - 1), 0);
        MMAALL(1);
    }

    // epilogue
    #pragma unroll
    for (int m = 0; m < 4; m++) {
        int r0 = row0 + wm*64 + m*16 + g;
        #pragma unroll
        for (int n = 0; n < 4; n++) {
            int c = col0 + wn*32 + n*8 + tg*2;
            float b0f = bias ? bias[c] : 0.0f;
            float b1f = bias ? bias[c + 1] : 0.0f;
            float v[4] = { acc[m][n][0] + b0f, acc[m][n][1] + b1f,
                           acc[m][n][2] + b0f, acc[m][n][3] + b1f };
            if (mode & 1) {
                #pragma unroll
                for (int i = 0; i < 4; i++)
                    v[i] = 0.5f * v[i] * (1.0f + erff(v[i] * 0.70710678118654752f));
            }
            if (mode & 2) {
                int r1 = r0 + 8;
                if ((r0 & 1023) < sp[r0 >> 10]) { v[0] = 0.0f; v[1] = 0.0f; }
                if ((r1 & 1023) < sp[r1 >> 10]) { v[2] = 0.0f; v[3] = 0.0f; }
            }
            if (mode & 4) {
                #pragma unroll
                for (int i = 0; i < 4; i++) v[i] = tf32r(v[i]);
            }
            *(float2*)&C[(size_t)r0 * ldc + c]       = make_float2(v[0], v[1]);
            *(float2*)&C[(size_t)(r0 + 8) * ldc + c] = make_float2(v[2], v[3]);
        }
    }
}

// =================================================================================
// Flash attention (round-4 version, unchanged)
// =================================================================================
#define FA_LDK 72
#define FA_LDP 132
#define FA_KV (128*FA_LDK)
#define FA_SMEM ((4*FA_KV + 128*FA_LDP)*4)

__global__ void __launch_bounds__(256,1) flash_attn(
    const float* __restrict__ Q, const float* __restrict__ Kg,
    const float* __restrict__ Vg, float* __restrict__ O,
    const int* __restrict__ sp)
{
    int z = blockIdx.z, bi = z >> 4, hi = z & 15;
    int q0 = blockIdx.x * 128;
    const float* Qb = Q  + (size_t)bi*SS*DD + hi*DKK;
    const float* Kb = Kg + (size_t)bi*SS*DD + hi*DKK;
    const float* Vb = Vg + (size_t)bi*SS*DD + hi*DKK;
    float* Ob = O + (size_t)bi*SS*DD + hi*DKK;

    extern __shared__ float sm[];
    float* Ks = sm;
    float* Vs = sm + 2*FA_KV;
    float* Ps = sm + 4*FA_KV;
    uint32_t sBase = (uint32_t)__cvta_generic_to_shared(sm);

    int tid = threadIdx.x;
    int lane = tid & 31, warp = tid >> 5;
    int g = lane >> 2, tg = lane & 3;
    int wq = warp * 16;
    int spv = sp[bi];
    float slope = exp2f(-0.5f * (float)(hi + 1));

    #pragma unroll
    for (int p = 0; p < 8; p++) {
        int i = tid + (p << 8);
        int r = i >> 4, c = (i & 15) << 2;
        *(float4*)&Ps[r*FA_LDK + c] = *(const float4*)(Qb + (size_t)(q0 + r)*DD + c);
    }
    __syncthreads();
    uint32_t aq[8][4];
    #pragma unroll
    for (int kf = 0; kf < 8; kf++) {
        const float* p = Ps + (wq + g)*FA_LDK + kf*8 + tg;
        aq[kf][0] = __float_as_uint(p[0]);
        aq[kf][1] = __float_as_uint(p[8*FA_LDK]);
        aq[kf][2] = __float_as_uint(p[4]);
        aq[kf][3] = __float_as_uint(p[8*FA_LDK + 4]);
    }
    __syncthreads();

    int nt = (q0 >= 256) ? (q0 >> 7) + 1 : 8;

    {
        #pragma unroll
        for (int p = 0; p < 8; p++) {
            int i = tid + (p << 8);
            int r = i >> 4, c = (i & 15) << 2;
            cp16(sBase + (uint32_t)(r*FA_LDK + c)*4,            Kb + (size_t)r*DD + c);
            cp16(sBase + (uint32_t)(2*FA_KV + r*FA_LDK + c)*4,  Vb + (size_t)r*DD + c);
        }
        CP_COMMIT();
    }

    float m_i[2] = {-1e30f, -1e30f};
    float l_i[2] = {0.0f, 0.0f};
    float acc_o[8][4] = {};
    float* Pw = Ps + wq*FA_LDP;

    for (int t = 0; t < nt; t++) {
        __syncthreads();
        if (t + 1 < nt) {
            int st = (t + 1) & 1;
            const float* Kt = Kb + (size_t)((t+1) << 7)*DD;
            const float* Vt = Vb + (size_t)((t+1) << 7)*DD;
            #pragma unroll
            for (int p = 0; p < 8; p++) {
                int i = tid + (p << 8);
                int r = i >> 4, c = (i & 15) << 2;
                cp16(sBase + (uint32_t)(st*FA_KV + r*FA_LDK + c)*4,     Kt + (size_t)r*DD + c);
                cp16(sBase + (uint32_t)((2+st)*FA_KV + r*FA_LDK + c)*4, Vt + (size_t)r*DD + c);
            }
        }
        CP_COMMIT();
        CP_WAIT1();
        __syncthreads();

        const float* ks = Ks + (t & 1)*FA_KV;
        const float* vs = Vs + (t & 1)*FA_KV;

        float acc_s[16][4] = {};
        #pragma unroll
        for (int kf = 0; kf < 8; kf++) {
            int kc = kf << 3;
            #pragma unroll
            for (int nf = 0; nf < 16; nf++) {
                uint32_t bf[2];
                const float* p = ks + (nf*8 + g)*FA_LDK + kc + tg;
                bf[0] = __float_as_uint(p[0]);
                bf[1] = __float_as_uint(p[4]);
                mma_tf32(acc_s[nf], aq[kf], bf);
            }
        }

        int c0 = t << 7;
        int qr0 = q0 + wq + g, qr1 = qr0 + 8;
        float tm0 = -1e30f, tm1 = -1e30f;
        #pragma unroll
        for (int nf = 0; nf < 16; nf++) {
            int c = c0 + nf*8 + tg*2;
            #pragma unroll
            for (int j = 0; j < 2; j++) {
                int cc = c + j;
                float s0 = acc_s[nf][j]   * 0.125f + slope * (float)(cc - qr0);
                float s1 = acc_s[nf][j+2] * 0.125f + slope * (float)(cc - qr1);
                bool ok0 = (qr0 >= cc) || (qr0 < spv) || (cc < spv);
                bool ok1 = (qr1 >= cc) || (qr1 < spv) || (cc < spv);
                acc_s[nf][j]   = ok0 ? s0 : -1e9f;
                acc_s[nf][j+2] = ok1 ? s1 : -1e9f;
                tm0 = fmaxf(tm0, acc_s[nf][j]);
                tm1 = fmaxf(tm1, acc_s[nf][j+2]);
            }
        }
        tm0 = fmaxf(tm0, __shfl_xor_sync(0xffffffffu, tm0, 1));
        tm0 = fmaxf(tm0, __shfl_xor_sync(0xffffffffu, tm0, 2));
        tm1 = fmaxf(tm1, __shfl_xor_sync(0xffffffffu, tm1, 1));
        tm1 = fmaxf(tm1, __shfl_xor_sync(0xffffffffu, tm1, 2));

        float mn0 = fmaxf(m_i[0], tm0), mn1 = fmaxf(m_i[1], tm1);
        float al0 = expf(m_i[0] - mn0),  al1 = expf(m_i[1] - mn1);
        m_i[0] = mn0; m_i[1] = mn1;

        float rs0 = 0.0f, rs1 = 0.0f;
        #pragma unroll
        for (int nf = 0; nf < 16; nf++) {
            float p0 = expf(acc_s[nf][0] - mn0);
            float p1 = expf(acc_s[nf][1] - mn0);
            float p2 = expf(acc_s[nf][2] - mn1);
            float p3 = expf(acc_s[nf][3] - mn1);
            rs0 += p0 + p1; rs1 += p2 + p3;
            int col = nf*8 + tg*2;
            *(float2*)&Pw[g*FA_LDP + col]       = make_float2(tf32r(p0), tf32r(p1));
            *(float2*)&Pw[(g+8)*FA_LDP + col]   = make_float2(tf32r(p2), tf32r(p3));
        }
        rs0 += __shfl_xor_sync(0xffffffffu, rs0, 1);
        rs0 += __shfl_xor_sync(0xffffffffu, rs0, 2);
        rs1 += __shfl_xor_sync(0xffffffffu, rs1, 1);
        rs1 += __shfl_xor_sync(0xffffffffu, rs1, 2);
        l_i[0] = l_i[0]*al0 + rs0;
        l_i[1] = l_i[1]*al1 + rs1;

        #pragma unroll
        for (int nf = 0; nf < 8; nf++) {
            acc_o[nf][0] *= al0; acc_o[nf][1] *= al0;
            acc_o[nf][2] *= al1; acc_o[nf][3] *= al1;
        }
        __syncwarp();

        #pragma unroll
        for (int kf = 0; kf < 16; kf++) {
            int kc = kf << 3;
            uint32_t af[4];
            const float* p = Pw + g*FA_LDP + kc + tg;
            af[0] = __float_as_uint(p[0]);
            af[1] = __float_as_uint(p[8*FA_LDP]);
            af[2] = __float_as_uint(p[4]);
            af[3] = __float_as_uint(p[8*FA_LDP + 4]);
            #pragma unroll
            for (int nf = 0; nf < 8; nf++) {
                uint32_t bf[2];
                const float* q2 = vs + (kc + tg)*FA_LDK + nf*8 + g;
                bf[0] = __float_as_uint(q2[0]);
                bf[1] = __float_as_uint(q2[4*FA_LDK]);
                mma_tf32(acc_o[nf], af, bf);
            }
        }
        __syncwarp();
    }

    float inv0 = 1.0f / l_i[0], inv1 = 1.0f / l_i[1];
    int qr0 = q0 + wq + g;
    #pragma unroll
    for (int nf = 0; nf < 8; nf++) {
        int c = nf*8 + tg*2;
        *(float2*)&Ob[(size_t)qr0*DD + c] =
            make_float2(tf32r(acc_o[nf][0]*inv0), tf32r(acc_o[nf][1]*inv0));
        *(float2*)&Ob[(size_t)(qr0+8)*DD + c] =
            make_float2(tf32r(acc_o[nf][2]*inv1), tf32r(acc_o[nf][3]*inv1));
    }
}

// ---------------- residual add + layernorm; writes fp32 out + tf32 out_t --------
__global__ void __launch_bounds__(256) add_ln(
    const float* __restrict__ X, const float* __restrict__ Rs,
    const float* __restrict__ g, const float* __restrict__ bta,
    float* __restrict__ out, float* __restrict__ out_t)
{
    int r = blockIdx.x, tid = threadIdx.x;
    const float4* x4 = (const float4*)(X + (size_t)r * DD);
    const float4* r4 = (const float4*)(Rs + (size_t)r * DD);
    float4 xv = x4[tid], rv = r4[tid];
    float v0 = xv.x + rv.x, v1 = xv.y + rv.y, v2 = xv.z + rv.z, v3 = xv.w + rv.w;
    float s1 = v0 + v1 + v2 + v3;
    float s2 = v0*v0 + v1*v1 + v2*v2 + v3*v3;

    __shared__ float rA[256], rB[256];
    rA[tid] = s1; rB[tid] = s2; __syncthreads();
    for (int s = 128; s > 0; s >>= 1) {
        if (tid < s) { rA[tid] += rA[tid + s]; rB[tid] += rB[tid + s]; }
        __syncthreads();
    }
    float mu = rA[0] * (1.0f / 1024.0f);
    float var = rB[0] * (1.0f / 1024.0f) - mu * mu;
    float rstd = rsqrtf(var + 1e-5f);

    const float4 gv = ((const float4*)g)[tid];
    const float4 bv = ((const float4*)bta)[tid];
    float4 o;
    o.x = (v0 - mu) * rstd * gv.x + bv.x;
    o.y = (v1 - mu) * rstd * gv.y + bv.y;
    o.z = (v2 - mu) * rstd * gv.z + bv.z;
    o.w = (v3 - mu) * rstd * gv.w + bv.w;
    ((float4*)(out + (size_t)r * DD))[tid] = o;
    float4 t = make_float4(tf32r(o.x), tf32r(o.y), tf32r(o.z), tf32r(o.w));
    ((float4*)(out_t + (size_t)r * DD))[tid] = t;
}

// ---------------- launch ----------------
extern "C" void kernel_launch(void* const* d_in, const int* in_sizes, int n_in,
                              void* d_out, int out_size) {
    (void)in_sizes; (void)n_in; (void)out_size;
    const int*   x    = (const int*)  d_in[0];
    const int*   sp   = (const int*)  d_in[1];
    const float* emb  = (const float*)d_in[2];
    const float* Wq   = (const float*)d_in[3];
    const float* bq   = (const float*)d_in[4];
    const float* Wk   = (const float*)d_in[5];
    const float* bk   = (const float*)d_in[6];
    const float* Wv   = (const float*)d_in[7];
    const float* bv   = (const float*)d_in[8];
    const float* Wo   = (const float*)d_in[9];
    const float* bo   = (const float*)d_in[10];
    const float* ln1g = (const float*)d_in[11];
    const float* ln1b = (const float*)d_in[12];
    const float* W1   = (const float*)d_in[13];
    const float* b1   = (const float*)d_in[14];
    const float* W2   = (const float*)d_in[15];
    const float* b2   = (const float*)d_in[16];
    const float* ln2g = (const float*)d_in[17];
    const float* ln2b = (const float*)d_in[18];
    const float* fcw  = (const float*)d_in[19];
    const float* fcb  = (const float*)d_in[20];
    float* out = (float*)d_out;

    float *h, *ht, *q, *k, *v, *attn, *tmp, *ffn;
    cudaGetSymbolAddress((void**)&h,    g_h);
    cudaGetSymbolAddress((void**)&ht,   g_ht);
    cudaGetSymbolAddress((void**)&q,    g_q);
    cudaGetSymbolAddress((void**)&k,    g_k);
    cudaGetSymbolAddress((void**)&v,    g_v);
    cudaGetSymbolAddress((void**)&attn, g_attn);
    cudaGetSymbolAddress((void**)&tmp,  g_tmp);
    cudaGetSymbolAddress((void**)&ffn,  g_ffn);

    static int attr_done = 0;
    if (!attr_done) {
        cudaFuncSetAttribute(gemm_tc,    cudaFuncAttributeMaxDynamicSharedMemorySize, GEMM_SMEM);
        cudaFuncSetAttribute(flash_attn, cudaFuncAttributeMaxDynamicSharedMemorySize, FA_SMEM);
        attr_done = 1;
    }

    const float* NUL = 0;
    float* NULF = 0;

    embed_kernel<<<MTOK, 256>>>(x, emb, h, ht);

    for (int l = 0; l < LL; l++) {
        const float* Wql = Wq + (size_t)l * DD * DD;
        const float* Wkl = Wk + (size_t)l * DD * DD;
        const float* Wvl = Wv + (size_t)l * DD * DD;
        const float* Wol = Wo + (size_t)l * DD * DD;
        const float* W1l = W1 + (size_t)l * DD * DFFN;
        const float* W2l = W2 + (size_t)l * DFFN * DD;

        // fused QKV (grid 384)
        gemm_tc<<<dim3(MTOK/128, DD/128, 3), 256, GEMM_SMEM>>>(
            ht,
            Wql, bq + (size_t)l*DD, q,
            Wkl, bk + (size_t)l*DD, k,
            Wvl, bv + (size_t)l*DD, v,
            DD, DD, DD, DD, 4, (const int*)0);

        flash_attn<<<dim3(SS/128, 1, BB*HH), 256, FA_SMEM>>>(q, k, v, attn, sp);

        gemm_tc<<<dim3(MTOK/128, DD/128, 1), 256, GEMM_SMEM>>>(
            attn, Wol, bo + (size_t)l*DD, tmp, NUL, NUL, NULF, NUL, NUL, NULF,
            DD, DD, DD, DD, 0, (const int*)0);
        add_ln<<<MTOK, 256>>>(h, tmp, ln1g + (size_t)l*DD, ln1b + (size_t)l*DD, h, ht);

        gemm_tc<<<dim3(MTOK/128, DFFN/128, 1), 256, GEMM_SMEM>>>(
            ht, W1l, b1 + (size_t)l*DFFN, ffn, NUL, NUL, NULF, NUL, NUL, NULF,
            DD, DD, DFFN, DFFN, 1 | 4, (const int*)0);
        gemm_tc<<<dim3(MTOK/128, DD/128, 1), 256, GEMM_SMEM>>>(
            ffn, W2l, b2 + (size_t)l*DD, tmp, NUL, NUL, NULF, NUL, NUL, NULF,
            DFFN, DFFN, DD, DD, 0, (const int*)0);
        add_ln<<<MTOK, 256>>>(h, tmp, ln2g + (size_t)l*DD, ln2b + (size_t)l*DD, h, ht);
    }

    gemm_tc<<<dim3(MTOK/128, OUTV/128, 1), 256, GEMM_SMEM>>>(
        ht, fcw, fcb, out, NUL, NUL, NULF, NUL, NUL, NULF,
        DD, DD, OUTV, OUTV, 2, sp);
}